// round 13
// baseline (speedup 1.0000x reference)
#include <cuda_runtime.h>
#include <cuda_fp16.h>
#include <cstdint>

// v (4, 2048, 12, 64) f32, w (12, 2048) f32.  seq_len = 2046.
// pbv[n,j,h,d] = sum_l w[h,|l-j|] * v[n,l,h,d], zero at j,l in {0,2047}
// z_pb[j,h]    = w[h,0] + P[j-1] + P[2046-j]
//
// R13: R12 (fp16 single-product, 4 warps x 64 j-rows, 4 m-tiles/warp,
// 3-stage cp.async ring) + __launch_bounds__(128,3): regs 172->170 so
// 3 CTAs/SM fit -> all 384 CTAs resident in ONE wave, 3 warps/SMSP.

#define B_ 4
#define S_ 2048
#define H_ 12
#define D_ 64

// gmem scratch
__device__ __align__(16) uint32_t g_vp[1536 * 2048];  // v fp16 chunk tiles
__device__ __align__(16) uint32_t g_wh[H_ * 4096];    // per-head A pair table

// dynamic smem layout (bytes)
#define OFF_WHX 0
#define OFF_BUF 16384
#define SM_TOTAL (16384 + 3 * 8192)   // 40960

__device__ __forceinline__ uint32_t smem_u32(const void* p) {
    uint32_t a;
    asm("{ .reg .u64 t; cvta.to.shared.u64 t, %1; cvt.u32.u64 %0, t; }"
        : "=r"(a) : "l"(p));
    return a;
}
__device__ __forceinline__ void mma16816(float* c, uint32_t a0, uint32_t a1,
                                         uint32_t a2, uint32_t a3,
                                         const uint32_t* b) {
    asm volatile(
        "mma.sync.aligned.m16n8k16.row.col.f32.f16.f16.f32 "
        "{%0,%1,%2,%3}, {%4,%5,%6,%7}, {%8,%9}, {%0,%1,%2,%3};"
        : "+f"(c[0]), "+f"(c[1]), "+f"(c[2]), "+f"(c[3])
        : "r"(a0), "r"(a1), "r"(a2), "r"(a3), "r"(b[0]), "r"(b[1]));
}
__device__ __forceinline__ void ldsm4t(uint32_t* r, uint32_t addr) {
    asm volatile(
        "ldmatrix.sync.aligned.m8n8.x4.trans.shared.b16 {%0,%1,%2,%3}, [%4];"
        : "=r"(r[0]), "=r"(r[1]), "=r"(r[2]), "=r"(r[3]) : "r"(addr));
}
__device__ __forceinline__ void cp16(uint32_t dst, const void* src) {
    asm volatile("cp.async.cg.shared.global [%0], [%1], 16;"
                 :: "r"(dst), "l"(src) : "memory");
}
__device__ __forceinline__ int iabs_(int x) { return x < 0 ? -x : x; }
__device__ __forceinline__ uint32_t f16bits(float x) {
    __half_raw hr = __half_raw(__float2half_rn(x));
    return (uint32_t)hr.x;
}

// ------- pre-pass: vconv (0..1535) + zpb (1536..1547) + A tables (1548..1559) ----
__global__ void __launch_bounds__(256) pre_kernel(
    const float* __restrict__ v, const float* __restrict__ w,
    float* __restrict__ z)
{
    __shared__ float P[2048];
    __shared__ float csum[256];
    const int tid = threadIdx.x;

    if (blockIdx.x < 1536) {
        // ---- v -> swizzled fp16 chunk tiles ----
        const int blk = blockIdx.x;       // (n*12+h)*32 + kc
        const int kc = blk & 31;
        const int nh = blk >> 5;
        const int h = nh % H_, n = nh / H_;
        const int vr = tid >> 2;          // row in chunk 0..63
        const int cseg = tid & 3;         // 16-float segment
        const int l = kc * 64 + vr;

        const float4* src = (const float4*)(v +
            ((size_t)(n * S_ + l) * H_ + h) * D_ + cseg * 16);
        float4 p0 = src[0], p1 = src[1], p2 = src[2], p3 = src[3];
        float f[16];
        f[0]=p0.x; f[1]=p0.y; f[2]=p0.z; f[3]=p0.w;
        f[4]=p1.x; f[5]=p1.y; f[6]=p1.z; f[7]=p1.w;
        f[8]=p2.x; f[9]=p2.y; f[10]=p2.z; f[11]=p2.w;
        f[12]=p3.x; f[13]=p3.y; f[14]=p3.z; f[15]=p3.w;
        if (l == 0 || l == S_ - 1) {
#pragma unroll
            for (int i = 0; i < 16; ++i) f[i] = 0.f;
        }
        uint32_t* base = g_vp + (size_t)blk * 2048;
#pragma unroll
        for (int cchunk = 0; cchunk < 2; ++cchunk) {
            uint32_t u[4];
#pragma unroll
            for (int p = 0; p < 4; ++p) {
                __half2 hp = __floats2half2_rn(f[cchunk * 8 + 2 * p],
                                               f[cchunk * 8 + 2 * p + 1]);
                u[p] = *(uint32_t*)&hp;
            }
            int cc = cseg * 2 + cchunk;
            int idx = vr * 32 + ((cc ^ (vr & 7)) << 2);
            *(uint4*)&base[idx] = make_uint4(u[0], u[1], u[2], u[3]);
        }
        return;
    }

    if (blockIdx.x >= 1548) {
        // ---- A pair table for head h ----
        const int h = blockIdx.x - 1548;
        const float* wrow = w + (size_t)h * S_;
        uint32_t* dst = g_wh + (size_t)h * 4096;
        for (int i = tid; i < 4096; i += 256) {
            int m0 = iabs_(i - 2048);
            int m1 = iabs_(i - 2047);
            float e0 = (m0 < 2046) ? wrow[m0] : 0.f;
            float e1 = (m1 < 2046) ? wrow[m1] : 0.f;
            dst[i] = f16bits(e0) | (f16bits(e1) << 16);
        }
        return;
    }

    // ---- z_pb for head h ----
    const int h = blockIdx.x - 1536;
    const float* wrow = w + (size_t)h * S_;

    float loc[8];
    float run = 0.f;
#pragma unroll
    for (int i = 0; i < 8; ++i) {
        int m = 1 + 8 * tid + i;
        float x = (m < 2046) ? wrow[m] : 0.f;
        run += x;
        loc[i] = run;
    }
    csum[tid] = run;
    __syncthreads();
    if (tid == 0) {
        float s = 0.f;
        for (int t = 0; t < 256; ++t) { float cc = csum[t]; csum[t] = s; s += cc; }
    }
    __syncthreads();
    float base = csum[tid];
#pragma unroll
    for (int i = 0; i < 8; ++i) {
        int t = 1 + 8 * tid + i;
        if (t < 2048) P[t] = base + loc[i];
    }
    if (tid == 0) P[0] = 0.f;
    __syncthreads();

    const float w0 = wrow[0];
    for (int j = tid; j < S_; j += 256) {
        float zv = (j == 0 || j == S_ - 1) ? 0.f : (w0 + P[j - 1] + P[2046 - j]);
        z[(size_t)j * H_ + h] = zv;
    }
}

// ------- main kernel: 128 threads, 4 warps x 64 j-rows, 3 CTAs/SM ----
__global__ void __launch_bounds__(128, 3) pbv_mma_kernel(float* __restrict__ out)
{
    extern __shared__ char smem[];
    uint32_t* whx = (uint32_t*)(smem + OFF_WHX);

    const int tid  = threadIdx.x;
    const int lane = tid & 31;
    const int wid  = tid >> 5;
    const int jt = blockIdx.x, h = blockIdx.y, n = blockIdx.z;
    const int j0 = jt * 256;
    const int nh32 = (n * H_ + h) * 32;

    const uint32_t sb = smem_u32(smem);
    const uint32_t bufb0 = sb + OFF_BUF;

    // ---- preload: A table (16KB, own group) + chunks 0,1 ----
    {
        const char* tsrc = (const char*)(g_wh + (size_t)h * 4096) + tid * 16;
        uint32_t tdst = sb + OFF_WHX + tid * 16;
#pragma unroll
        for (int i = 0; i < 8; ++i)
            cp16(tdst + i * 2048, tsrc + i * 2048);
        const char* src = (const char*)(g_vp + (size_t)nh32 * 2048) + tid * 16;
        uint32_t dst = bufb0 + tid * 16;
#pragma unroll
        for (int i = 0; i < 4; ++i)
            cp16(dst + i * 2048, src + i * 2048);
        asm volatile("cp.async.commit_group;" ::: "memory");
        uint32_t dst1 = bufb0 + 8192 + tid * 16;
#pragma unroll
        for (int i = 0; i < 4; ++i)
            cp16(dst1 + i * 2048, src + 8192 + i * 2048);
        asm volatile("cp.async.commit_group;" ::: "memory");
    }

    // accumulators: 4 m-tiles x 8 n-tiles x 4 = 128 floats
    float c[4][8][4];
#pragma unroll
    for (int m = 0; m < 4; ++m)
#pragma unroll
        for (int t = 0; t < 8; ++t)
#pragma unroll
            for (int p = 0; p < 4; ++p) c[m][t][p] = 0.f;

    // ldmatrix lane mapping
    const int rb = lane & 15;
    const int co = lane >> 4;
    const int xr = rb & 7;
    const uint32_t rowoff = (uint32_t)rb * 128u;

    // A fragment mapping: warp covers j rows [jw, jw+64)
    const int g = lane >> 2, q = lane & 3;
    const int jw = j0 + wid * 64;
    const int qg = 2 * q - (jw + g) + 2048;

    for (int kc = 0; kc < 32; ++kc) {
        asm volatile("cp.async.wait_group 1;" ::: "memory");
        __syncthreads();

        // issue loads for chunk kc+2 (ring slot (kc+2)%3)
        if (kc + 2 < 32) {
            const char* src = (const char*)(g_vp +
                (size_t)(nh32 + kc + 2) * 2048) + tid * 16;
            uint32_t dst = bufb0 + ((kc + 2) % 3) * 8192 + tid * 16;
#pragma unroll
            for (int i = 0; i < 4; ++i)
                cp16(dst + i * 2048, src + i * 2048);
        }
        asm volatile("cp.async.commit_group;" ::: "memory");

        const uint32_t vb = bufb0 + (kc % 3) * 8192;

#pragma unroll
        for (int s = 0; s < 4; ++s) {
            const int i0 = qg + kc * 64 + s * 16;
            // 9 LDS (stride 8) cover all 4 m-tiles' A fragments (Toeplitz)
            uint32_t wA[9];
#pragma unroll
            for (int k = 0; k < 9; ++k)
                wA[k] = whx[i0 + 8 - 8 * k];

            uint32_t bh[16];
            const uint32_t soff = (uint32_t)s * 2048u + rowoff;
#pragma unroll
            for (int t4 = 0; t4 < 4; ++t4) {
                uint32_t chunk = (uint32_t)((t4 * 2 + co) ^ xr);
                ldsm4t(&bh[t4 * 4], vb + soff + chunk * 16u);
            }
            // 32 independent MMAs per s-step
#pragma unroll
            for (int t = 0; t < 8; ++t) {
                const uint32_t* bhp = &bh[(t >> 1) * 4 + (t & 1) * 2];
#pragma unroll
                for (int tm = 0; tm < 4; ++tm) {
                    // m-tile tm: rows jw+16*tm .. +15
                    mma16816(c[tm][t], wA[2 * tm + 1], wA[2 * tm + 2],
                             wA[2 * tm], wA[2 * tm + 1], bhp);
                }
            }
        }
    }

    // ---- epilogue ----
#pragma unroll
    for (int m = 0; m < 4; ++m) {
        const int row0 = jw + m * 16 + g;
        const int row1 = row0 + 8;
        const bool z0 = (row0 == 0) | (row0 == S_ - 1);
        const bool z1 = (row1 == 0) | (row1 == S_ - 1);
        float* o0 = out + ((size_t)(n * S_ + row0) * H_ + h) * D_ + q * 2;
        float* o1 = out + ((size_t)(n * S_ + row1) * H_ + h) * D_ + q * 2;
#pragma unroll
        for (int t = 0; t < 8; ++t) {
            float2 u0 = z0 ? make_float2(0.f, 0.f)
                           : make_float2(c[m][t][0], c[m][t][1]);
            float2 u1 = z1 ? make_float2(0.f, 0.f)
                           : make_float2(c[m][t][2], c[m][t][3]);
            *(float2*)(o0 + t * 8) = u0;
            *(float2*)(o1 + t * 8) = u1;
        }
    }
}

extern "C" void kernel_launch(void* const* d_in, const int* in_sizes, int n_in,
                              void* d_out, int out_size) {
    const float* v = (const float*)d_in[0];
    const float* w = (const float*)d_in[1];
    if (n_in >= 2 && in_sizes[0] < in_sizes[1]) {
        const float* t = v; v = w; w = t;
    }
    float* out = (float*)d_out;
    float* z   = out + (size_t)B_ * S_ * H_ * D_;

    cudaFuncSetAttribute(pbv_mma_kernel,
                         cudaFuncAttributeMaxDynamicSharedMemorySize, SM_TOTAL);

    pre_kernel<<<1536 + 2 * H_, 256>>>(v, w, z);
    dim3 grid(S_ / 256, H_, B_);
    pbv_mma_kernel<<<grid, 128, SM_TOTAL>>>(out);
}

// round 15
// speedup vs baseline: 1.1393x; 1.1393x over previous
#include <cuda_runtime.h>
#include <cuda_fp16.h>
#include <cstdint>

// v (4, 2048, 12, 64) f32, w (12, 2048) f32.  seq_len = 2046.
// pbv[n,j,h,d] = sum_l w[h,|l-j|] * v[n,l,h,d], zero at j,l in {0,2047}
// z_pb[j,h]    = w[h,0] + P[j-1] + P[2046-j]
//
// R14: R12 compute core (fp16 single-product, 4 warps x 64 j-rows,
// 4 m-tiles/warp) but BARRIER-FREE main loop: each warp streams its own
// private copy of each 8KB B-chunk through a per-warp 3-slot cp.async
// ring (wait_group + syncwarp only). Chunks are L2-hot so the 4x
// redundant traffic is cheap; warps fully decoupled.

#define B_ 4
#define S_ 2048
#define H_ 12
#define D_ 64

// gmem scratch
__device__ __align__(16) uint32_t g_vp[1536 * 2048];  // v fp16 chunk tiles
__device__ __align__(16) uint32_t g_wh[H_ * 4096];    // per-head A pair table

// dynamic smem layout (bytes)
#define OFF_WHX 0
#define OFF_WBUF 16384                        // 4 warps x 3 slots x 8192
#define SM_TOTAL (16384 + 4 * 3 * 8192)       // 114688

__device__ __forceinline__ uint32_t smem_u32(const void* p) {
    uint32_t a;
    asm("{ .reg .u64 t; cvta.to.shared.u64 t, %1; cvt.u32.u64 %0, t; }"
        : "=r"(a) : "l"(p));
    return a;
}
__device__ __forceinline__ void mma16816(float* c, uint32_t a0, uint32_t a1,
                                         uint32_t a2, uint32_t a3,
                                         const uint32_t* b) {
    asm volatile(
        "mma.sync.aligned.m16n8k16.row.col.f32.f16.f16.f32 "
        "{%0,%1,%2,%3}, {%4,%5,%6,%7}, {%8,%9}, {%0,%1,%2,%3};"
        : "+f"(c[0]), "+f"(c[1]), "+f"(c[2]), "+f"(c[3])
        : "r"(a0), "r"(a1), "r"(a2), "r"(a3), "r"(b[0]), "r"(b[1]));
}
__device__ __forceinline__ void ldsm4t(uint32_t* r, uint32_t addr) {
    asm volatile(
        "ldmatrix.sync.aligned.m8n8.x4.trans.shared.b16 {%0,%1,%2,%3}, [%4];"
        : "=r"(r[0]), "=r"(r[1]), "=r"(r[2]), "=r"(r[3]) : "r"(addr));
}
__device__ __forceinline__ void cp16(uint32_t dst, const void* src) {
    asm volatile("cp.async.cg.shared.global [%0], [%1], 16;"
                 :: "r"(dst), "l"(src) : "memory");
}
__device__ __forceinline__ int iabs_(int x) { return x < 0 ? -x : x; }
__device__ __forceinline__ uint32_t f16bits(float x) {
    __half_raw hr = __half_raw(__float2half_rn(x));
    return (uint32_t)hr.x;
}

// ------- pre-pass: vconv (0..1535) + zpb (1536..1547) + A tables (1548..1559) ----
__global__ void __launch_bounds__(256) pre_kernel(
    const float* __restrict__ v, const float* __restrict__ w,
    float* __restrict__ z)
{
    __shared__ float P[2048];
    __shared__ float csum[256];
    const int tid = threadIdx.x;

    if (blockIdx.x < 1536) {
        // ---- v -> swizzled fp16 chunk tiles ----
        const int blk = blockIdx.x;       // (n*12+h)*32 + kc
        const int kc = blk & 31;
        const int nh = blk >> 5;
        const int h = nh % H_, n = nh / H_;
        const int vr = tid >> 2;          // row in chunk 0..63
        const int cseg = tid & 3;         // 16-float segment
        const int l = kc * 64 + vr;

        const float4* src = (const float4*)(v +
            ((size_t)(n * S_ + l) * H_ + h) * D_ + cseg * 16);
        float4 p0 = src[0], p1 = src[1], p2 = src[2], p3 = src[3];
        float f[16];
        f[0]=p0.x; f[1]=p0.y; f[2]=p0.z; f[3]=p0.w;
        f[4]=p1.x; f[5]=p1.y; f[6]=p1.z; f[7]=p1.w;
        f[8]=p2.x; f[9]=p2.y; f[10]=p2.z; f[11]=p2.w;
        f[12]=p3.x; f[13]=p3.y; f[14]=p3.z; f[15]=p3.w;
        if (l == 0 || l == S_ - 1) {
#pragma unroll
            for (int i = 0; i < 16; ++i) f[i] = 0.f;
        }
        uint32_t* base = g_vp + (size_t)blk * 2048;
#pragma unroll
        for (int cchunk = 0; cchunk < 2; ++cchunk) {
            uint32_t u[4];
#pragma unroll
            for (int p = 0; p < 4; ++p) {
                __half2 hp = __floats2half2_rn(f[cchunk * 8 + 2 * p],
                                               f[cchunk * 8 + 2 * p + 1]);
                u[p] = *(uint32_t*)&hp;
            }
            int cc = cseg * 2 + cchunk;
            int idx = vr * 32 + ((cc ^ (vr & 7)) << 2);
            *(uint4*)&base[idx] = make_uint4(u[0], u[1], u[2], u[3]);
        }
        return;
    }

    if (blockIdx.x >= 1548) {
        // ---- A pair table for head h ----
        const int h = blockIdx.x - 1548;
        const float* wrow = w + (size_t)h * S_;
        uint32_t* dst = g_wh + (size_t)h * 4096;
        for (int i = tid; i < 4096; i += 256) {
            int m0 = iabs_(i - 2048);
            int m1 = iabs_(i - 2047);
            float e0 = (m0 < 2046) ? wrow[m0] : 0.f;
            float e1 = (m1 < 2046) ? wrow[m1] : 0.f;
            dst[i] = f16bits(e0) | (f16bits(e1) << 16);
        }
        return;
    }

    // ---- z_pb for head h ----
    const int h = blockIdx.x - 1536;
    const float* wrow = w + (size_t)h * S_;

    float loc[8];
    float run = 0.f;
#pragma unroll
    for (int i = 0; i < 8; ++i) {
        int m = 1 + 8 * tid + i;
        float x = (m < 2046) ? wrow[m] : 0.f;
        run += x;
        loc[i] = run;
    }
    csum[tid] = run;
    __syncthreads();
    if (tid == 0) {
        float s = 0.f;
        for (int t = 0; t < 256; ++t) { float cc = csum[t]; csum[t] = s; s += cc; }
    }
    __syncthreads();
    float base = csum[tid];
#pragma unroll
    for (int i = 0; i < 8; ++i) {
        int t = 1 + 8 * tid + i;
        if (t < 2048) P[t] = base + loc[i];
    }
    if (tid == 0) P[0] = 0.f;
    __syncthreads();

    const float w0 = wrow[0];
    for (int j = tid; j < S_; j += 256) {
        float zv = (j == 0 || j == S_ - 1) ? 0.f : (w0 + P[j - 1] + P[2046 - j]);
        z[(size_t)j * H_ + h] = zv;
    }
}

// ------- main kernel: 128 threads, 4 warps x 64 j-rows, barrier-free loop ----
__global__ void __launch_bounds__(128) pbv_mma_kernel(float* __restrict__ out)
{
    extern __shared__ char smem[];
    uint32_t* whx = (uint32_t*)(smem + OFF_WHX);

    const int tid  = threadIdx.x;
    const int lane = tid & 31;
    const int wid  = tid >> 5;
    const int jt = blockIdx.x, h = blockIdx.y, n = blockIdx.z;
    const int j0 = jt * 256;
    const int nh32 = (n * H_ + h) * 32;

    const uint32_t sb = smem_u32(smem);
    // per-warp 3-slot ring
    const uint32_t wbuf = sb + OFF_WBUF + (uint32_t)wid * 24576u;

    // gmem chunk stream base for this (n,h), per-lane 16B slot
    const char* vbase = (const char*)(g_vp + (size_t)nh32 * 2048) + lane * 16;

    // ---- group 0: A table (cooperative, 8 x 16B per thread) ----
    {
        const char* tsrc = (const char*)(g_wh + (size_t)h * 4096) + tid * 16;
        uint32_t tdst = sb + OFF_WHX + tid * 16;
#pragma unroll
        for (int i = 0; i < 8; ++i)
            cp16(tdst + i * 2048, tsrc + i * 2048);
        asm volatile("cp.async.commit_group;" ::: "memory");
    }
    // ---- groups 1,2: per-warp copies of chunks 0,1 ----
#pragma unroll
    for (int pc = 0; pc < 2; ++pc) {
        const char* src = vbase + (size_t)pc * 8192;
        uint32_t dst = wbuf + pc * 8192 + lane * 16;
#pragma unroll
        for (int i = 0; i < 16; ++i)
            cp16(dst + i * 512, src + i * 512);
        asm volatile("cp.async.commit_group;" ::: "memory");
    }
    // table (group 0) done once at most 2 groups pend; barrier for whx visibility
    asm volatile("cp.async.wait_group 2;" ::: "memory");
    __syncthreads();

    // accumulators: 4 m-tiles x 8 n-tiles x 4 = 128 floats
    float c[4][8][4];
#pragma unroll
    for (int m = 0; m < 4; ++m)
#pragma unroll
        for (int t = 0; t < 8; ++t)
#pragma unroll
            for (int p = 0; p < 4; ++p) c[m][t][p] = 0.f;

    // ldmatrix lane mapping
    const int rb = lane & 15;
    const int co = lane >> 4;
    const int xr = rb & 7;
    const uint32_t rowoff = (uint32_t)rb * 128u;

    // A fragment mapping: warp covers j rows [jw, jw+64)
    const int g = lane >> 2, q = lane & 3;
    const int jw = j0 + wid * 64;
    const int qg = 2 * q - (jw + g) + 2048;

    for (int kc = 0; kc < 32; ++kc) {
        // issue chunk kc+2 into slot (kc+2)%3 (held kc-1, already consumed)
        if (kc + 2 < 32) {
            const char* src = vbase + (size_t)(kc + 2) * 8192;
            uint32_t dst = wbuf + ((kc + 2) % 3) * 8192 + lane * 16;
#pragma unroll
            for (int i = 0; i < 16; ++i)
                cp16(dst + i * 512, src + i * 512);
        }
        asm volatile("cp.async.commit_group;" ::: "memory");
        // chunk kc's group done when at most 2 newer groups pend
        asm volatile("cp.async.wait_group 2;" ::: "memory");
        __syncwarp();

        const uint32_t vb = wbuf + (kc % 3) * 8192;

#pragma unroll
        for (int s = 0; s < 4; ++s) {
            const int i0 = qg + kc * 64 + s * 16;
            // 9 LDS (stride 8) cover all 4 m-tiles' A fragments (Toeplitz)
            uint32_t wA[9];
#pragma unroll
            for (int k = 0; k < 9; ++k)
                wA[k] = whx[i0 + 8 - 8 * k];

            uint32_t bh[16];
            const uint32_t soff = (uint32_t)s * 2048u + rowoff;
#pragma unroll
            for (int t4 = 0; t4 < 4; ++t4) {
                uint32_t chunk = (uint32_t)((t4 * 2 + co) ^ xr);
                ldsm4t(&bh[t4 * 4], vb + soff + chunk * 16u);
            }
            // 32 independent MMAs per s-step
#pragma unroll
            for (int t = 0; t < 8; ++t) {
                const uint32_t* bhp = &bh[(t >> 1) * 4 + (t & 1) * 2];
#pragma unroll
                for (int tm = 0; tm < 4; ++tm) {
                    mma16816(c[tm][t], wA[2 * tm + 1], wA[2 * tm + 2],
                             wA[2 * tm], wA[2 * tm + 1], bhp);
                }
            }
        }
    }

    // ---- epilogue ----
#pragma unroll
    for (int m = 0; m < 4; ++m) {
        const int row0 = jw + m * 16 + g;
        const int row1 = row0 + 8;
        const bool z0 = (row0 == 0) | (row0 == S_ - 1);
        const bool z1 = (row1 == 0) | (row1 == S_ - 1);
        float* o0 = out + ((size_t)(n * S_ + row0) * H_ + h) * D_ + q * 2;
        float* o1 = out + ((size_t)(n * S_ + row1) * H_ + h) * D_ + q * 2;
#pragma unroll
        for (int t = 0; t < 8; ++t) {
            float2 u0 = z0 ? make_float2(0.f, 0.f)
                           : make_float2(c[m][t][0], c[m][t][1]);
            float2 u1 = z1 ? make_float2(0.f, 0.f)
                           : make_float2(c[m][t][2], c[m][t][3]);
            *(float2*)(o0 + t * 8) = u0;
            *(float2*)(o1 + t * 8) = u1;
        }
    }
}

extern "C" void kernel_launch(void* const* d_in, const int* in_sizes, int n_in,
                              void* d_out, int out_size) {
    const float* v = (const float*)d_in[0];
    const float* w = (const float*)d_in[1];
    if (n_in >= 2 && in_sizes[0] < in_sizes[1]) {
        const float* t = v; v = w; w = t;
    }
    float* out = (float*)d_out;
    float* z   = out + (size_t)B_ * S_ * H_ * D_;

    cudaFuncSetAttribute(pbv_mma_kernel,
                         cudaFuncAttributeMaxDynamicSharedMemorySize, SM_TOTAL);

    pre_kernel<<<1536 + 2 * H_, 256>>>(v, w, z);
    dim3 grid(S_ / 256, H_, B_);
    pbv_mma_kernel<<<grid, 128, SM_TOTAL>>>(out);
}

// round 16
// speedup vs baseline: 1.2363x; 1.0851x over previous
#include <cuda_runtime.h>
#include <cuda_fp16.h>
#include <cstdint>

// v (4, 2048, 12, 64) f32, w (12, 2048) f32.  seq_len = 2046.
// pbv[n,j,h,d] = sum_l w[h,|l-j|] * v[n,l,h,d], zero at j,l in {0,2047}
// z_pb[j,h]    = w[h,0] + P[j-1] + P[2046-j]
//
// R16: persistent scheduling. 296 CTAs (=2/SM, exactly one wave) statically
// process the 384 256-j tile-units: CTA k does unit k, and unit k+296 if
// k<88. Inner loop = R12 (fp16 single-product, 4 warps x 64 j-rows,
// 4 m-tiles/warp, 3-stage cp.async ring, per-head A table).

#define B_ 4
#define S_ 2048
#define H_ 12
#define D_ 64
#define NUNITS 384
#define NWORK  296

// gmem scratch
__device__ __align__(16) uint32_t g_vp[1536 * 2048];  // v fp16 chunk tiles
__device__ __align__(16) uint32_t g_wh[H_ * 4096];    // per-head A pair table

// dynamic smem layout (bytes)
#define OFF_WHX 0
#define OFF_BUF 16384
#define SM_TOTAL (16384 + 3 * 8192)   // 40960

__device__ __forceinline__ uint32_t smem_u32(const void* p) {
    uint32_t a;
    asm("{ .reg .u64 t; cvta.to.shared.u64 t, %1; cvt.u32.u64 %0, t; }"
        : "=r"(a) : "l"(p));
    return a;
}
__device__ __forceinline__ void mma16816(float* c, uint32_t a0, uint32_t a1,
                                         uint32_t a2, uint32_t a3,
                                         const uint32_t* b) {
    asm volatile(
        "mma.sync.aligned.m16n8k16.row.col.f32.f16.f16.f32 "
        "{%0,%1,%2,%3}, {%4,%5,%6,%7}, {%8,%9}, {%0,%1,%2,%3};"
        : "+f"(c[0]), "+f"(c[1]), "+f"(c[2]), "+f"(c[3])
        : "r"(a0), "r"(a1), "r"(a2), "r"(a3), "r"(b[0]), "r"(b[1]));
}
__device__ __forceinline__ void ldsm4t(uint32_t* r, uint32_t addr) {
    asm volatile(
        "ldmatrix.sync.aligned.m8n8.x4.trans.shared.b16 {%0,%1,%2,%3}, [%4];"
        : "=r"(r[0]), "=r"(r[1]), "=r"(r[2]), "=r"(r[3]) : "r"(addr));
}
__device__ __forceinline__ void cp16(uint32_t dst, const void* src) {
    asm volatile("cp.async.cg.shared.global [%0], [%1], 16;"
                 :: "r"(dst), "l"(src) : "memory");
}
__device__ __forceinline__ int iabs_(int x) { return x < 0 ? -x : x; }
__device__ __forceinline__ uint32_t f16bits(float x) {
    __half_raw hr = __half_raw(__float2half_rn(x));
    return (uint32_t)hr.x;
}

// ------- pre-pass: vconv (0..1535) + zpb (1536..1547) + A tables (1548..1559) ----
__global__ void __launch_bounds__(256) pre_kernel(
    const float* __restrict__ v, const float* __restrict__ w,
    float* __restrict__ z)
{
    __shared__ float P[2048];
    __shared__ float csum[256];
    const int tid = threadIdx.x;

    if (blockIdx.x < 1536) {
        // ---- v -> swizzled fp16 chunk tiles ----
        const int blk = blockIdx.x;       // (n*12+h)*32 + kc
        const int kc = blk & 31;
        const int nh = blk >> 5;
        const int h = nh % H_, n = nh / H_;
        const int vr = tid >> 2;          // row in chunk 0..63
        const int cseg = tid & 3;         // 16-float segment
        const int l = kc * 64 + vr;

        const float4* src = (const float4*)(v +
            ((size_t)(n * S_ + l) * H_ + h) * D_ + cseg * 16);
        float4 p0 = src[0], p1 = src[1], p2 = src[2], p3 = src[3];
        float f[16];
        f[0]=p0.x; f[1]=p0.y; f[2]=p0.z; f[3]=p0.w;
        f[4]=p1.x; f[5]=p1.y; f[6]=p1.z; f[7]=p1.w;
        f[8]=p2.x; f[9]=p2.y; f[10]=p2.z; f[11]=p2.w;
        f[12]=p3.x; f[13]=p3.y; f[14]=p3.z; f[15]=p3.w;
        if (l == 0 || l == S_ - 1) {
#pragma unroll
            for (int i = 0; i < 16; ++i) f[i] = 0.f;
        }
        uint32_t* base = g_vp + (size_t)blk * 2048;
#pragma unroll
        for (int cchunk = 0; cchunk < 2; ++cchunk) {
            uint32_t u[4];
#pragma unroll
            for (int p = 0; p < 4; ++p) {
                __half2 hp = __floats2half2_rn(f[cchunk * 8 + 2 * p],
                                               f[cchunk * 8 + 2 * p + 1]);
                u[p] = *(uint32_t*)&hp;
            }
            int cc = cseg * 2 + cchunk;
            int idx = vr * 32 + ((cc ^ (vr & 7)) << 2);
            *(uint4*)&base[idx] = make_uint4(u[0], u[1], u[2], u[3]);
        }
        return;
    }

    if (blockIdx.x >= 1548) {
        // ---- A pair table for head h ----
        const int h = blockIdx.x - 1548;
        const float* wrow = w + (size_t)h * S_;
        uint32_t* dst = g_wh + (size_t)h * 4096;
        for (int i = tid; i < 4096; i += 256) {
            int m0 = iabs_(i - 2048);
            int m1 = iabs_(i - 2047);
            float e0 = (m0 < 2046) ? wrow[m0] : 0.f;
            float e1 = (m1 < 2046) ? wrow[m1] : 0.f;
            dst[i] = f16bits(e0) | (f16bits(e1) << 16);
        }
        return;
    }

    // ---- z_pb for head h ----
    const int h = blockIdx.x - 1536;
    const float* wrow = w + (size_t)h * S_;

    float loc[8];
    float run = 0.f;
#pragma unroll
    for (int i = 0; i < 8; ++i) {
        int m = 1 + 8 * tid + i;
        float x = (m < 2046) ? wrow[m] : 0.f;
        run += x;
        loc[i] = run;
    }
    csum[tid] = run;
    __syncthreads();
    if (tid == 0) {
        float s = 0.f;
        for (int t = 0; t < 256; ++t) { float cc = csum[t]; csum[t] = s; s += cc; }
    }
    __syncthreads();
    float base = csum[tid];
#pragma unroll
    for (int i = 0; i < 8; ++i) {
        int t = 1 + 8 * tid + i;
        if (t < 2048) P[t] = base + loc[i];
    }
    if (tid == 0) P[0] = 0.f;
    __syncthreads();

    const float w0 = wrow[0];
    for (int j = tid; j < S_; j += 256) {
        float zv = (j == 0 || j == S_ - 1) ? 0.f : (w0 + P[j - 1] + P[2046 - j]);
        z[(size_t)j * H_ + h] = zv;
    }
}

// ------- main kernel: persistent, 296 CTAs, units of 256 j ----
__global__ void __launch_bounds__(128) pbv_mma_kernel(float* __restrict__ out)
{
    extern __shared__ char smem[];
    uint32_t* whx = (uint32_t*)(smem + OFF_WHX);

    const int tid  = threadIdx.x;
    const int lane = tid & 31;
    const int wid  = tid >> 5;

    const uint32_t sb = smem_u32(smem);
    const uint32_t bufb0 = sb + OFF_BUF;

    // ldmatrix lane mapping (unit-invariant)
    const int rb = lane & 15;
    const int co = lane >> 4;
    const int xr = rb & 7;
    const uint32_t rowoff = (uint32_t)rb * 128u;
    const int g = lane >> 2, q = lane & 3;

    for (int rep = 0; rep < 2; ++rep) {
        const int u = blockIdx.x + rep * NWORK;
        if (u >= NUNITS) break;
        // unit u -> (n, h, jt): 8 jt per (n,h)
        const int jt = u & 7;
        const int h  = (u >> 3) % H_;
        const int n  = u / (8 * H_);
        const int j0 = jt * 256;
        const int nh32 = (n * H_ + h) * 32;

        // ---- preload: A table (16KB) + chunk0 in group0; chunk1 in group1 ----
        {
            const char* tsrc = (const char*)(g_wh + (size_t)h * 4096) + tid * 16;
            uint32_t tdst = sb + OFF_WHX + tid * 16;
#pragma unroll
            for (int i = 0; i < 8; ++i)
                cp16(tdst + i * 2048, tsrc + i * 2048);
            const char* src = (const char*)(g_vp + (size_t)nh32 * 2048) + tid * 16;
            uint32_t dst = bufb0 + tid * 16;
#pragma unroll
            for (int i = 0; i < 4; ++i)
                cp16(dst + i * 2048, src + i * 2048);
            asm volatile("cp.async.commit_group;" ::: "memory");
            uint32_t dst1 = bufb0 + 8192 + tid * 16;
#pragma unroll
            for (int i = 0; i < 4; ++i)
                cp16(dst1 + i * 2048, src + 8192 + i * 2048);
            asm volatile("cp.async.commit_group;" ::: "memory");
        }

        // accumulators: 4 m-tiles x 8 n-tiles x 4 = 128 floats
        float c[4][8][4];
#pragma unroll
        for (int m = 0; m < 4; ++m)
#pragma unroll
            for (int t = 0; t < 8; ++t)
#pragma unroll
                for (int p = 0; p < 4; ++p) c[m][t][p] = 0.f;

        // A fragment mapping: warp covers j rows [jw, jw+64)
        const int jw = j0 + wid * 64;
        const int qg = 2 * q - (jw + g) + 2048;

        for (int kc = 0; kc < 32; ++kc) {
            asm volatile("cp.async.wait_group 1;" ::: "memory");
            __syncthreads();

            // issue loads for chunk kc+2 (ring slot (kc+2)%3)
            if (kc + 2 < 32) {
                const char* src = (const char*)(g_vp +
                    (size_t)(nh32 + kc + 2) * 2048) + tid * 16;
                uint32_t dst = bufb0 + ((kc + 2) % 3) * 8192 + tid * 16;
#pragma unroll
                for (int i = 0; i < 4; ++i)
                    cp16(dst + i * 2048, src + i * 2048);
            }
            asm volatile("cp.async.commit_group;" ::: "memory");

            const uint32_t vb = bufb0 + (kc % 3) * 8192;

#pragma unroll
            for (int s = 0; s < 4; ++s) {
                const int i0 = qg + kc * 64 + s * 16;
                // 9 LDS (stride 8) cover all 4 m-tiles' A fragments (Toeplitz)
                uint32_t wA[9];
#pragma unroll
                for (int k = 0; k < 9; ++k)
                    wA[k] = whx[i0 + 8 - 8 * k];

                uint32_t bh[16];
                const uint32_t soff = (uint32_t)s * 2048u + rowoff;
#pragma unroll
                for (int t4 = 0; t4 < 4; ++t4) {
                    uint32_t chunk = (uint32_t)((t4 * 2 + co) ^ xr);
                    ldsm4t(&bh[t4 * 4], vb + soff + chunk * 16u);
                }
                // 32 independent MMAs per s-step
#pragma unroll
                for (int t = 0; t < 8; ++t) {
                    const uint32_t* bhp = &bh[(t >> 1) * 4 + (t & 1) * 2];
#pragma unroll
                    for (int tm = 0; tm < 4; ++tm) {
                        mma16816(c[tm][t], wA[2 * tm + 1], wA[2 * tm + 2],
                                 wA[2 * tm], wA[2 * tm + 1], bhp);
                    }
                }
            }
        }

        // ---- epilogue for this unit ----
#pragma unroll
        for (int m = 0; m < 4; ++m) {
            const int row0 = jw + m * 16 + g;
            const int row1 = row0 + 8;
            const bool z0 = (row0 == 0) | (row0 == S_ - 1);
            const bool z1 = (row1 == 0) | (row1 == S_ - 1);
            float* o0 = out + ((size_t)(n * S_ + row0) * H_ + h) * D_ + q * 2;
            float* o1 = out + ((size_t)(n * S_ + row1) * H_ + h) * D_ + q * 2;
#pragma unroll
            for (int t = 0; t < 8; ++t) {
                float2 u0 = z0 ? make_float2(0.f, 0.f)
                               : make_float2(c[m][t][0], c[m][t][1]);
                float2 u1 = z1 ? make_float2(0.f, 0.f)
                               : make_float2(c[m][t][2], c[m][t][3]);
                *(float2*)(o0 + t * 8) = u0;
                *(float2*)(o1 + t * 8) = u1;
            }
        }

        // guard: next unit's preload overwrites whx + ring buffers
        __syncthreads();
    }
}

extern "C" void kernel_launch(void* const* d_in, const int* in_sizes, int n_in,
                              void* d_out, int out_size) {
    const float* v = (const float*)d_in[0];
    const float* w = (const float*)d_in[1];
    if (n_in >= 2 && in_sizes[0] < in_sizes[1]) {
        const float* t = v; v = w; w = t;
    }
    float* out = (float*)d_out;
    float* z   = out + (size_t)B_ * S_ * H_ * D_;

    cudaFuncSetAttribute(pbv_mma_kernel,
                         cudaFuncAttributeMaxDynamicSharedMemorySize, SM_TOTAL);

    pre_kernel<<<1536 + 2 * H_, 256>>>(v, w, z);
    pbv_mma_kernel<<<NWORK, 128, SM_TOTAL>>>(out);
}

// round 17
// speedup vs baseline: 1.2385x; 1.0018x over previous
#include <cuda_runtime.h>
#include <cuda_fp16.h>
#include <cstdint>

// v (4, 2048, 12, 64) f32, w (12, 2048) f32.  seq_len = 2046.
// pbv[n,j,h,d] = sum_l w[h,|l-j|] * v[n,l,h,d], zero at j,l in {0,2047}
// z_pb[j,h]    = w[h,0] + P[j-1] + P[2046-j]
//
// R17: R16 persistent schedule (296 CTAs, 384 units of 256 j, max 3/SM)
// with: TK=128 chunks (16 iters, half the barrier convoy) and a
// double-buffered A table prefetched across units (serial ramp hidden).

#define B_ 4
#define S_ 2048
#define H_ 12
#define D_ 64
#define NUNITS 384
#define NWORK  296
#define NCH    16            // 16 chunks of 128 l

// gmem scratch
__device__ __align__(16) uint32_t g_vp[1536 * 2048];  // v fp16 tiles (8KB per 64 l)
__device__ __align__(16) uint32_t g_wh[H_ * 4096];    // per-head A pair table

// dynamic smem layout (bytes)
#define OFF_WHX0 0
#define OFF_WHX1 16384
#define OFF_BUF  32768               // 3 slots x 16384
#define SM_TOTAL (32768 + 3 * 16384) // 81920

__device__ __forceinline__ uint32_t smem_u32(const void* p) {
    uint32_t a;
    asm("{ .reg .u64 t; cvta.to.shared.u64 t, %1; cvt.u32.u64 %0, t; }"
        : "=r"(a) : "l"(p));
    return a;
}
__device__ __forceinline__ void mma16816(float* c, uint32_t a0, uint32_t a1,
                                         uint32_t a2, uint32_t a3,
                                         const uint32_t* b) {
    asm volatile(
        "mma.sync.aligned.m16n8k16.row.col.f32.f16.f16.f32 "
        "{%0,%1,%2,%3}, {%4,%5,%6,%7}, {%8,%9}, {%0,%1,%2,%3};"
        : "+f"(c[0]), "+f"(c[1]), "+f"(c[2]), "+f"(c[3])
        : "r"(a0), "r"(a1), "r"(a2), "r"(a3), "r"(b[0]), "r"(b[1]));
}
__device__ __forceinline__ void ldsm4t(uint32_t* r, uint32_t addr) {
    asm volatile(
        "ldmatrix.sync.aligned.m8n8.x4.trans.shared.b16 {%0,%1,%2,%3}, [%4];"
        : "=r"(r[0]), "=r"(r[1]), "=r"(r[2]), "=r"(r[3]) : "r"(addr));
}
__device__ __forceinline__ void cp16(uint32_t dst, const void* src) {
    asm volatile("cp.async.cg.shared.global [%0], [%1], 16;"
                 :: "r"(dst), "l"(src) : "memory");
}
__device__ __forceinline__ int iabs_(int x) { return x < 0 ? -x : x; }
__device__ __forceinline__ uint32_t f16bits(float x) {
    __half_raw hr = __half_raw(__float2half_rn(x));
    return (uint32_t)hr.x;
}

// ------- pre-pass: vconv (0..1535) + zpb (1536..1547) + A tables (1548..1559) ----
__global__ void __launch_bounds__(256) pre_kernel(
    const float* __restrict__ v, const float* __restrict__ w,
    float* __restrict__ z)
{
    __shared__ float P[2048];
    __shared__ float csum[256];
    const int tid = threadIdx.x;

    if (blockIdx.x < 1536) {
        const int blk = blockIdx.x;       // (n*12+h)*32 + kc
        const int kc = blk & 31;
        const int nh = blk >> 5;
        const int h = nh % H_, n = nh / H_;
        const int vr = tid >> 2;
        const int cseg = tid & 3;
        const int l = kc * 64 + vr;

        const float4* src = (const float4*)(v +
            ((size_t)(n * S_ + l) * H_ + h) * D_ + cseg * 16);
        float4 p0 = src[0], p1 = src[1], p2 = src[2], p3 = src[3];
        float f[16];
        f[0]=p0.x; f[1]=p0.y; f[2]=p0.z; f[3]=p0.w;
        f[4]=p1.x; f[5]=p1.y; f[6]=p1.z; f[7]=p1.w;
        f[8]=p2.x; f[9]=p2.y; f[10]=p2.z; f[11]=p2.w;
        f[12]=p3.x; f[13]=p3.y; f[14]=p3.z; f[15]=p3.w;
        if (l == 0 || l == S_ - 1) {
#pragma unroll
            for (int i = 0; i < 16; ++i) f[i] = 0.f;
        }
        uint32_t* base = g_vp + (size_t)blk * 2048;
#pragma unroll
        for (int cchunk = 0; cchunk < 2; ++cchunk) {
            uint32_t u[4];
#pragma unroll
            for (int p = 0; p < 4; ++p) {
                __half2 hp = __floats2half2_rn(f[cchunk * 8 + 2 * p],
                                               f[cchunk * 8 + 2 * p + 1]);
                u[p] = *(uint32_t*)&hp;
            }
            int cc = cseg * 2 + cchunk;
            int idx = vr * 32 + ((cc ^ (vr & 7)) << 2);
            *(uint4*)&base[idx] = make_uint4(u[0], u[1], u[2], u[3]);
        }
        return;
    }

    if (blockIdx.x >= 1548) {
        const int h = blockIdx.x - 1548;
        const float* wrow = w + (size_t)h * S_;
        uint32_t* dst = g_wh + (size_t)h * 4096;
        for (int i = tid; i < 4096; i += 256) {
            int m0 = iabs_(i - 2048);
            int m1 = iabs_(i - 2047);
            float e0 = (m0 < 2046) ? wrow[m0] : 0.f;
            float e1 = (m1 < 2046) ? wrow[m1] : 0.f;
            dst[i] = f16bits(e0) | (f16bits(e1) << 16);
        }
        return;
    }

    // ---- z_pb for head h ----
    const int h = blockIdx.x - 1536;
    const float* wrow = w + (size_t)h * S_;

    float loc[8];
    float run = 0.f;
#pragma unroll
    for (int i = 0; i < 8; ++i) {
        int m = 1 + 8 * tid + i;
        float x = (m < 2046) ? wrow[m] : 0.f;
        run += x;
        loc[i] = run;
    }
    csum[tid] = run;
    __syncthreads();
    if (tid == 0) {
        float s = 0.f;
        for (int t = 0; t < 256; ++t) { float cc = csum[t]; csum[t] = s; s += cc; }
    }
    __syncthreads();
    float base = csum[tid];
#pragma unroll
    for (int i = 0; i < 8; ++i) {
        int t = 1 + 8 * tid + i;
        if (t < 2048) P[t] = base + loc[i];
    }
    if (tid == 0) P[0] = 0.f;
    __syncthreads();

    const float w0 = wrow[0];
    for (int j = tid; j < S_; j += 256) {
        float zv = (j == 0 || j == S_ - 1) ? 0.f : (w0 + P[j - 1] + P[2046 - j]);
        z[(size_t)j * H_ + h] = zv;
    }
}

// ------- main kernel: persistent, 296 CTAs, units of 256 j, TK=128 ----
__global__ void __launch_bounds__(128) pbv_mma_kernel(float* __restrict__ out)
{
    extern __shared__ char smem[];

    const int tid  = threadIdx.x;
    const int lane = tid & 31;
    const int wid  = tid >> 5;

    const uint32_t sb = smem_u32(smem);
    const uint32_t bufb0 = sb + OFF_BUF;

    // ldmatrix lane mapping (unit-invariant)
    const int rb = lane & 15;
    const int co = lane >> 4;
    const int xr = rb & 7;
    const uint32_t rowoff = (uint32_t)rb * 128u;
    const int g = lane >> 2, q = lane & 3;

    // unit decode helper values for unit 0 of this CTA
    // (unit u -> jt = u&7, h = (u>>3)%12, n = u/96)

    // ---- prefetch A table for first unit into buffer 0 ----
    {
        const int u0 = blockIdx.x;
        const int h0 = (u0 >> 3) % H_;
        const char* tsrc = (const char*)(g_wh + (size_t)h0 * 4096) + tid * 16;
        uint32_t tdst = sb + OFF_WHX0 + tid * 16;
#pragma unroll
        for (int i = 0; i < 8; ++i)
            cp16(tdst + i * 2048, tsrc + i * 2048);
        asm volatile("cp.async.commit_group;" ::: "memory");
    }

    for (int rep = 0; rep < 2; ++rep) {
        const int u = blockIdx.x + rep * NWORK;
        if (u >= NUNITS) break;
        const int jt = u & 7;
        const int h  = (u >> 3) % H_;
        const int n  = u / (8 * H_);
        const int j0 = jt * 256;
        // byte base of this (n,h)'s 256KB chunk stream
        const char* vsrc = (const char*)(g_vp + (size_t)((n * H_ + h) * 32) * 2048);

        uint32_t* whx = (uint32_t*)(smem + (rep ? OFF_WHX1 : OFF_WHX0));

        // ---- preload chunks 0,1 (16KB each) into slots 0,1 ----
#pragma unroll
        for (int pc = 0; pc < 2; ++pc) {
            const char* src = vsrc + (size_t)pc * 16384 + tid * 16;
            uint32_t dst = bufb0 + pc * 16384 + tid * 16;
#pragma unroll
            for (int i = 0; i < 8; ++i)
                cp16(dst + i * 2048, src + i * 2048);
            asm volatile("cp.async.commit_group;" ::: "memory");
        }

        // accumulators: 4 m-tiles x 8 n-tiles x 4 = 128 floats
        float c[4][8][4];
#pragma unroll
        for (int m = 0; m < 4; ++m)
#pragma unroll
            for (int t = 0; t < 8; ++t)
#pragma unroll
                for (int p = 0; p < 4; ++p) c[m][t][p] = 0.f;

        // A fragment mapping: warp covers j rows [jw, jw+64)
        const int jw = j0 + wid * 64;
        const int qg = 2 * q - (jw + g) + 2048;

        for (int kc = 0; kc < NCH; ++kc) {
            asm volatile("cp.async.wait_group 1;" ::: "memory");
            __syncthreads();

            // issue loads for chunk kc+2 (slot (kc+2)%3)
            if (kc + 2 < NCH) {
                const char* src = vsrc + (size_t)(kc + 2) * 16384 + tid * 16;
                uint32_t dst = bufb0 + ((kc + 2) % 3) * 16384 + tid * 16;
#pragma unroll
                for (int i = 0; i < 8; ++i)
                    cp16(dst + i * 2048, src + i * 2048);
            }
            asm volatile("cp.async.commit_group;" ::: "memory");

            const uint32_t vb = bufb0 + (kc % 3) * 16384;

#pragma unroll
            for (int s = 0; s < 8; ++s) {
                const int i0 = qg + kc * 128 + s * 16;
                // 9 LDS (stride 8) cover all 4 m-tiles' A fragments (Toeplitz)
                uint32_t wA[9];
#pragma unroll
                for (int k = 0; k < 9; ++k)
                    wA[k] = whx[i0 + 8 - 8 * k];

                uint32_t bh[16];
                const uint32_t soff = (uint32_t)s * 2048u + rowoff;
#pragma unroll
                for (int t4 = 0; t4 < 4; ++t4) {
                    uint32_t chunk = (uint32_t)((t4 * 2 + co) ^ xr);
                    ldsm4t(&bh[t4 * 4], vb + soff + chunk * 16u);
                }
                // 32 independent MMAs per s-step
#pragma unroll
                for (int t = 0; t < 8; ++t) {
                    const uint32_t* bhp = &bh[(t >> 1) * 4 + (t & 1) * 2];
#pragma unroll
                    for (int tm = 0; tm < 4; ++tm) {
                        mma16816(c[tm][t], wA[2 * tm + 1], wA[2 * tm + 2],
                                 wA[2 * tm], wA[2 * tm + 1], bhp);
                    }
                }
            }
        }

        // ---- prefetch next unit's A table into the other buffer ----
        if (rep == 0 && u + NWORK < NUNITS) {
            const int h1 = ((u + NWORK) >> 3) % H_;
            const char* tsrc = (const char*)(g_wh + (size_t)h1 * 4096) + tid * 16;
            uint32_t tdst = sb + OFF_WHX1 + tid * 16;
#pragma unroll
            for (int i = 0; i < 8; ++i)
                cp16(tdst + i * 2048, tsrc + i * 2048);
            asm volatile("cp.async.commit_group;" ::: "memory");
        }

        // ---- epilogue for this unit ----
#pragma unroll
        for (int m = 0; m < 4; ++m) {
            const int row0 = jw + m * 16 + g;
            const int row1 = row0 + 8;
            const bool z0 = (row0 == 0) | (row0 == S_ - 1);
            const bool z1 = (row1 == 0) | (row1 == S_ - 1);
            float* o0 = out + ((size_t)(n * S_ + row0) * H_ + h) * D_ + q * 2;
            float* o1 = out + ((size_t)(n * S_ + row1) * H_ + h) * D_ + q * 2;
#pragma unroll
            for (int t = 0; t < 8; ++t) {
                float2 u0 = z0 ? make_float2(0.f, 0.f)
                               : make_float2(c[m][t][0], c[m][t][1]);
                float2 u1 = z1 ? make_float2(0.f, 0.f)
                               : make_float2(c[m][t][2], c[m][t][3]);
                *(float2*)(o0 + t * 8) = u0;
                *(float2*)(o1 + t * 8) = u1;
            }
        }

        // guard: next unit's chunk preload overwrites ring slots 0,1
        __syncthreads();
    }
}

extern "C" void kernel_launch(void* const* d_in, const int* in_sizes, int n_in,
                              void* d_out, int out_size) {
    const float* v = (const float*)d_in[0];
    const float* w = (const float*)d_in[1];
    if (n_in >= 2 && in_sizes[0] < in_sizes[1]) {
        const float* t = v; v = w; w = t;
    }
    float* out = (float*)d_out;
    float* z   = out + (size_t)B_ * S_ * H_ * D_;

    cudaFuncSetAttribute(pbv_mma_kernel,
                         cudaFuncAttributeMaxDynamicSharedMemorySize, SM_TOTAL);

    pre_kernel<<<1536 + 2 * H_, 256>>>(v, w, z);
    pbv_mma_kernel<<<NWORK, 128, SM_TOTAL>>>(out);
}